// round 16
// baseline (speedup 1.0000x reference)
#include <cuda_runtime.h>

#define D_MODEL 4096
#define D_INNER 8192
#define D_STATE 16
#define DT_RANK 8
#define XP_DIM  (DT_RANK + 2 * D_STATE)   // 40

#define NSM        152            // GB300: 152 SMs
#define BLKS_PER_SM 5             // reg-limited residency at ~48 regs/256 thr
#define PERSIST_GRID (NSM * BLKS_PER_SM)   // 760

// ---------------- scratch (device globals; no allocation allowed) ------------
__device__ float g_x_conv[D_INNER];
__device__ float g_z[D_INNER];
__device__ float g_xp[XP_DIM];
__device__ float g_y[D_INNER];
__device__ float g_h_scratch[D_INNER * D_STATE];

// ---------------- helpers ----------------------------------------------------
__device__ __forceinline__ float warp_reduce(float v) {
#pragma unroll
    for (int o = 16; o; o >>= 1) v += __shfl_xor_sync(0xffffffffu, v, o);
    return v;
}

__device__ __forceinline__ float fma4(float4 w, float4 v, float a) {
    return fmaf(w.x, v.x, fmaf(w.y, v.y, fmaf(w.z, v.z, fmaf(w.w, v.w, a))));
}

__device__ __forceinline__ float sigmoidf_(float v) { return 1.f / (1.f + expf(-v)); }

// 8 KB chunk dot-product: 512 float4, lane-strided, 4 independent chains.
__device__ __forceinline__ float dot_chunk_8kb(
    const float4* __restrict__ Wr, const float4* __restrict__ vv, int lane)
{
    float a0 = 0.f, a1 = 0.f, a2 = 0.f, a3 = 0.f;
#pragma unroll
    for (int k = 0; k < 16; k += 4) {          // 512 float4 / 32 lanes = 16/lane
        const int b = k * 32 + lane;
        const float4 v0 = __ldg(&vv[b]);
        const float4 v1 = __ldg(&vv[b + 32]);
        const float4 v2 = __ldg(&vv[b + 64]);
        const float4 v3 = __ldg(&vv[b + 96]);
        const float4 w0 = Wr[b],      w1 = Wr[b + 32],
                     w2 = Wr[b + 64], w3 = Wr[b + 96];
        a0 = fma4(w0, v0, a0);  a1 = fma4(w1, v1, a1);
        a2 = fma4(w2, v2, a2);  a3 = fma4(w3, v3, a3);
    }
    return warp_reduce((a0 + a1) + (a2 + a3));
}

// ---------------- kernel 1: xz = W_in @ x, fused conv+silu epilogue ----------
// Persistent: 760 blocks loop over 4096 work items (block-stride).
// Per item: 8 warps = 2 channels x {x-row, z-row} x 2 half-row chunks (8KB).
__global__ void __launch_bounds__(256) k_gemv_in(
    const float* __restrict__ W,        // (16384, 4096)
    const float* __restrict__ x,        // (4096,)
    const float* __restrict__ cb,       // conv_buffer (8192, 3)
    const float* __restrict__ cw,       // conv_w (8192, 4)
    const float* __restrict__ conv_b)   // (8192,)
{
    const int warp = threadIdx.x >> 5, lane = threadIdx.x & 31;
    const int row_idx = warp >> 1;                 // 0..3: (c0,x)(c0,z)(c1,x)(c1,z)
    const int half    = warp & 1;                  // which 2048-float half
    const int ch_sub  = row_idx >> 1;              // 0..1
    const int is_z    = row_idx & 1;

    const float4* __restrict__ xv = (const float4*)x + half * 512;
    __shared__ float s[8];

    for (int it = blockIdx.x; it < D_INNER / 2; it += PERSIST_GRID) {
        const int ch  = it * 2 + ch_sub;
        const int row = ch + is_z * D_INNER;
        const float4* __restrict__ Wr =
            (const float4*)(W + (size_t)row * D_MODEL) + half * 512;

        const float part = dot_chunk_8kb(Wr, xv, lane);

        if (lane == 0) s[warp] = part;
        __syncthreads();

        if (threadIdx.x < 2) {
            const int t = threadIdx.x;
            const int c = it * 2 + t;
            const float accx = s[4 * t] + s[4 * t + 1];
            const float accz = s[4 * t + 2] + s[4 * t + 3];
            // conv_in = [cb[:,1], cb[:,2], v, v] ; weights [w0,w1,w2,w3]
            const float c1 = cb[c * 3 + 1];
            const float c2 = cb[c * 3 + 2];
            const float4 w4 = *(const float4*)(cw + c * 4);
            const float sv = fmaf(c1, w4.x, fmaf(c2, w4.y, fmaf(accx, w4.z + w4.w, conv_b[c])));
            g_x_conv[c] = sv * sigmoidf_(sv);   // silu
            g_z[c] = accz;
        }
        __syncthreads();   // protect s[] before next iteration
    }
}

// ---------------- kernel 2: xp = W_xp @ x_conv  (40 x 8192) ------------------
__global__ void __launch_bounds__(256) k_xp(const float* __restrict__ Wxp)
{
    const int row = blockIdx.x;                     // 0..39
    const float4* __restrict__ Wr = (const float4*)(Wxp + (size_t)row * D_INNER);
    const float4* __restrict__ xc = (const float4*)g_x_conv;

    float acc = 0.f;
    for (int idx = threadIdx.x; idx < D_INNER / 4; idx += 256) {
        acc = fma4(Wr[idx], xc[idx], acc);
    }
    __shared__ float sred[8];
    acc = warp_reduce(acc);
    if ((threadIdx.x & 31) == 0) sred[threadIdx.x >> 5] = acc;
    __syncthreads();
    if (threadIdx.x < 32) {
        float v = (threadIdx.x < 8) ? sred[threadIdx.x] : 0.f;
        v = warp_reduce(v);
        if (threadIdx.x == 0) g_xp[row] = v;
    }
}

// ---------------- kernel 3: dt/softplus + SSM state update + gate ------------
// One thread per channel (8192). Writes new_h and g_y.
__global__ void __launch_bounds__(256) k_state(
    const float* __restrict__ Wdt,      // (8192, 8)
    const float* __restrict__ bdt,      // (8192,)
    const float* __restrict__ Alog,     // (8192, 16)
    const float* __restrict__ h,        // ssm_state (8192, 16)
    const float* __restrict__ Dp,       // (8192,)
    float* __restrict__ newh)           // (8192, 16) or nullptr
{
    const int i = blockIdx.x * 256 + threadIdx.x;

    __shared__ float sxp[XP_DIM];
    if (threadIdx.x < XP_DIM) sxp[threadIdx.x] = g_xp[threadIdx.x];
    __syncthreads();

    // dt = softplus(W_dt[i,:] . xp[:8] + b_dt[i])
    const float4* wd = (const float4*)(Wdt + (size_t)i * DT_RANK);
    const float4 w0 = wd[0], w1 = wd[1];
    float dtin = bdt[i];
    dtin += w0.x * sxp[0] + w0.y * sxp[1] + w0.z * sxp[2] + w0.w * sxp[3]
          + w1.x * sxp[4] + w1.y * sxp[5] + w1.z * sxp[6] + w1.w * sxp[7];
    const float dt = (dtin > 20.f) ? dtin : log1pf(expf(dtin));

    const float xc = g_x_conv[i];
    const float* Ar = Alog + (size_t)i * D_STATE;
    const float* hr = h    + (size_t)i * D_STATE;
    float* nr = (newh ? newh : g_h_scratch) + (size_t)i * D_STATE;

    float acc = 0.f;
#pragma unroll
    for (int s = 0; s < D_STATE; s++) {
        const float abar = expf(-dt * expf(Ar[s]));               // exp(dt * -exp(A_log))
        const float nh = fmaf(abar, hr[s], dt * sxp[DT_RANK + s] * xc);
        nr[s] = nh;
        acc = fmaf(nh, sxp[DT_RANK + D_STATE + s], acc);
    }
    const float y = acc + Dp[i] * xc;
    const float z = g_z[i];
    g_y[i] = y * (z * sigmoidf_(z));
}

// ---------------- kernel 4: out = W_out @ y  (4096 x 8192) -------------------
// Persistent: 760 blocks loop over 2048 work items (block-stride).
// Per item: 8 warps = 2 rows x 4 quarter-row chunks (8KB).
__global__ void __launch_bounds__(256) k_gemv_out(
    const float* __restrict__ W, float* __restrict__ out)
{
    const int warp = threadIdx.x >> 5, lane = threadIdx.x & 31;
    const int row_idx = warp >> 2;                 // 0..1
    const int q       = warp & 3;                  // quarter 0..3

    const float4* __restrict__ yv = (const float4*)g_y + q * 512;
    __shared__ float s[8];

    for (int it = blockIdx.x; it < D_MODEL / 2; it += PERSIST_GRID) {
        const int r = it * 2 + row_idx;
        const float4* __restrict__ Wr =
            (const float4*)(W + (size_t)r * D_INNER) + q * 512;

        const float part = dot_chunk_8kb(Wr, yv, lane);

        if (lane == 0) s[warp] = part;
        __syncthreads();

        if (threadIdx.x < 2) {
            const int t = threadIdx.x;
            out[it * 2 + t] = s[4 * t] + s[4 * t + 1] + s[4 * t + 2] + s[4 * t + 3];
        }
        __syncthreads();   // protect s[] before next iteration
    }
}

// ---------------- launch ------------------------------------------------------
extern "C" void kernel_launch(void* const* d_in, const int* in_sizes, int n_in,
                              void* d_out, int out_size)
{
    const float* x       = (const float*)d_in[0];
    const float* h       = (const float*)d_in[1];   // ssm_state
    const float* cb      = (const float*)d_in[2];   // conv_buffer
    const float* W_in    = (const float*)d_in[3];
    const float* conv_w  = (const float*)d_in[4];
    const float* conv_b  = (const float*)d_in[5];
    const float* W_xp    = (const float*)d_in[6];
    const float* W_dt    = (const float*)d_in[7];
    const float* b_dt    = (const float*)d_in[8];
    const float* A_log   = (const float*)d_in[9];
    const float* D_param = (const float*)d_in[10];
    const float* W_out   = (const float*)d_in[11];

    float* out = (float*)d_out;
    // tuple output (out, new_h) concatenated: [4096][8192*16]
    float* newh = (out_size >= D_MODEL + D_INNER * D_STATE) ? (out + D_MODEL) : nullptr;

    k_gemv_in <<<PERSIST_GRID, 256>>>(W_in, x, cb, conv_w, conv_b);
    k_xp      <<<XP_DIM, 256>>>(W_xp);
    k_state   <<<D_INNER / 256, 256>>>(W_dt, b_dt, A_log, h, D_param, newh);
    k_gemv_out<<<PERSIST_GRID, 256>>>(W_out, out);
}